// round 14
// baseline (speedup 1.0000x reference)
#include <cuda_runtime.h>
#include <cuda_fp16.h>
#include <math.h>
#include <stdint.h>

// ---------------- dims ----------------
static const int Lc = 12, Hc = 12, Dc = 768, HDc = 64, Mc = 3072;
static const int IMGc = 384, Bc = 32, NCc = 1000;
static const int NP = 576;
static const int Sc = 577;
static const int BS = Bc * Sc;        // 18464
static const int GRID24 = 24;
static const int GS = 5;              // gemm pipeline stages

// ---------------- scratch ----------------
__device__ float g_t[BS * Dc];                 // residual (fp32)
__device__ float g_h[BS * Dc];                 // patchify gemm out (fp32)
// fp16 operands
__device__ __half g_h2[BS * Dc];
__device__ __half g_om2[BS * Dc];
__device__ __half g_mb2[(long long)BS * Mc];
__device__ __half g_qkv2[(long long)BS * 3 * Dc];
__device__ __half g_col2[Bc * NP * Dc];
__device__ __half g_cls2[Bc * Dc];
__device__ __half g_wq2[(long long)Lc * 3 * Dc * Dc];  // [l][n=2304][k=768]
__device__ __half g_cw2[Dc * Dc];                      // [n][k]
__device__ __half g_wm2[(long long)Lc * Dc * Dc];
__device__ __half g_w12[(long long)Lc * Mc * Dc];
__device__ __half g_w22[(long long)Lc * Dc * Mc];
__device__ __half g_wh2[NCc * Dc];

// ---------------- helpers ----------------
__device__ __forceinline__ void mma_f16(float c[4], const uint32_t a[4], const uint32_t b[2]) {
    asm volatile(
        "mma.sync.aligned.m16n8k16.row.col.f32.f16.f16.f32 "
        "{%0,%1,%2,%3}, {%4,%5,%6,%7}, {%8,%9}, {%0,%1,%2,%3};\n"
        : "+f"(c[0]), "+f"(c[1]), "+f"(c[2]), "+f"(c[3])
        : "r"(a[0]), "r"(a[1]), "r"(a[2]), "r"(a[3]), "r"(b[0]), "r"(b[1]));
}

__device__ __forceinline__ void cp_async16(void* smem_dst, const void* gsrc, int sz) {
    unsigned sm = (unsigned)__cvta_generic_to_shared(smem_dst);
    asm volatile("cp.async.cg.shared.global [%0], [%1], 16, %2;\n" :: "r"(sm), "l"(gsrc), "r"(sz));
}

__device__ __forceinline__ void ldsm4h(uint32_t r[4], const __half* p) {
    unsigned a = (unsigned)__cvta_generic_to_shared(p);
    asm volatile("ldmatrix.sync.aligned.m8n8.x4.shared.b16 {%0,%1,%2,%3}, [%4];\n"
                 : "=r"(r[0]), "=r"(r[1]), "=r"(r[2]), "=r"(r[3]) : "r"(a));
}
__device__ __forceinline__ void ldsm4h_trans(uint32_t r[4], const __half* p) {
    unsigned a = (unsigned)__cvta_generic_to_shared(p);
    asm volatile("ldmatrix.sync.aligned.m8n8.x4.trans.shared.b16 {%0,%1,%2,%3}, [%4];\n"
                 : "=r"(r[0]), "=r"(r[1]), "=r"(r[2]), "=r"(r[3]) : "r"(a));
}

// ---------------- fp16 tensor GEMM (R10 shape, GS=5) ----------------
static const int HROW = 40;
static const int HSTG = 128 * HROW;
static const int GEMM_SMEM = GS * 2 * HSTG * 2;  // 102400 bytes

__global__ void __launch_bounds__(256, 2)
hgemm_kernel(const __half* __restrict__ A, const __half* __restrict__ Bm,
             const float* __restrict__ bias, const float* __restrict__ res,
             const __half* __restrict__ res2,
             float* __restrict__ Cf, __half* __restrict__ C2,
             int M, int N, int K, int ldc, int act) {
    extern __shared__ __half smh[];

    int t = threadIdx.x;
    int lane = t & 31, wid = t >> 5;
    int wm = wid >> 2, wn = wid & 3;
    int g = lane >> 2, tig = lane & 3;
    int m0 = blockIdx.y * 128, n0 = blockIdx.x * 128;

    float acc[4][4][4] = {};
    int nk = K / 32;

    auto loadTile = [&](int k0, int s) {
        __half* dstA = smh + s * 2 * HSTG;
        __half* dstB = dstA + HSTG;
#pragma unroll
        for (int i = 0; i < 2; i++) {
            int c = t + i * 256;
            int r = c >> 2, sg = (c & 3) * 8;
            cp_async16(dstA + r * HROW + sg, A + (long long)(m0 + r) * K + k0 + sg,
                       (m0 + r < M) ? 16 : 0);
        }
#pragma unroll
        for (int i = 0; i < 2; i++) {
            int c = t + i * 256;
            int r = c >> 2, sg = (c & 3) * 8;
            cp_async16(dstB + r * HROW + sg, Bm + (long long)(n0 + r) * K + k0 + sg,
                       (n0 + r < N) ? 16 : 0);
        }
    };

#pragma unroll
    for (int s = 0; s < GS - 1; s++) {
        loadTile(s * 32, s);
        asm volatile("cp.async.commit_group;\n");
    }

    int a_row = wm * 64 + (lane & 15);
    int a_cofs = (lane >> 4) << 3;
    int b_row = wn * 32 + ((lane >> 4) << 3) + (lane & 7);
    int b_cofs = ((lane >> 3) & 1) << 3;

    for (int it = 0; it < nk; it++) {
        asm volatile("cp.async.wait_group %0;\n" :: "n"(GS - 2));
        __syncthreads();
        if (it + GS - 1 < nk) loadTile((it + GS - 1) * 32, (it + GS - 1) % GS);
        asm volatile("cp.async.commit_group;\n");

        const __half* Ab = smh + (it % GS) * 2 * HSTG;
        const __half* Bb = Ab + HSTG;
#pragma unroll
        for (int ks = 0; ks < 2; ks++) {
            int kc = ks * 16;
            uint32_t af[4][4], bq[2][4];
#pragma unroll
            for (int mt = 0; mt < 4; mt++)
                ldsm4h(af[mt], Ab + (a_row + mt * 16) * HROW + kc + a_cofs);
#pragma unroll
            for (int nb = 0; nb < 2; nb++)
                ldsm4h(bq[nb], Bb + (b_row + nb * 16) * HROW + kc + b_cofs);
#pragma unroll
            for (int mt = 0; mt < 4; mt++)
#pragma unroll
                for (int nt = 0; nt < 4; nt++) {
                    uint32_t b2[2] = { bq[nt >> 1][(nt & 1) * 2], bq[nt >> 1][(nt & 1) * 2 + 1] };
                    mma_f16(acc[mt][nt], af[mt], b2);
                }
        }
    }

#pragma unroll
    for (int mt = 0; mt < 4; mt++) {
#pragma unroll
        for (int nt = 0; nt < 4; nt++) {
            int row = m0 + wm * 64 + mt * 16 + g;
            int col = n0 + wn * 32 + nt * 8 + tig * 2;
#pragma unroll
            for (int cc = 0; cc < 4; cc++) {
                int m = row + (cc >> 1) * 8;
                int n = col + (cc & 1);
                if (m >= M || n >= N) continue;
                float v = acc[mt][nt][cc];
                if (bias) v += bias[n];
                if (res) v += res[(long long)m * ldc + n];
                if (res2) v += __half2float(res2[(long long)m * ldc + n]);
                if (act == 1) v = 0.5f * v * (1.0f + erff(v * 0.7071067811865476f));
                if (Cf) Cf[(long long)m * ldc + n] = v;
                if (C2) C2[(long long)m * ldc + n] = __float2half(v);
            }
        }
    }
}

// ---------------- fp16 flash attention: 3-stage K/V pipeline, Q frags hoisted ----------------
static const int FLASH_SMEM = (9216 + 9216 + 13824 + 13824) * 2;   // 92160 B

__global__ void __launch_bounds__(256)
flash_kernel(const __half* __restrict__ qkv, __half* __restrict__ om2) {
    extern __shared__ __half smh[];
    __half* Qs = smh;               // [128][72]
    __half* Ps = smh + 9216;        // [8][16][72]
    __half* Ks = smh + 18432;       // [3][64][72]
    __half* Vs = smh + 32256;       // [3][64][72]

    int qt = blockIdx.x, h = blockIdx.y, b = blockIdx.z;
    int t = threadIdx.x, lane = t & 31, w = t >> 5, g = lane >> 2, tig = lane & 3;
    const __half* qb = qkv + (long long)b * Sc * 2304 + h * 192;

#pragma unroll
    for (int i = 0; i < 4; i++) {
        int idx = t + i * 256;
        int row = idx >> 3, sg = idx & 7;
        int gr = qt * 128 + row;
        cp_async16(Qs + row * 72 + sg * 8, qb + (long long)gr * 2304 + sg * 8, gr < Sc ? 16 : 0);
    }
    auto issueKV = [&](int kt_, int buf) {
#pragma unroll
        for (int i = 0; i < 2; i++) {
            int idx = t + i * 256;
            int row = idx >> 3, sg = idx & 7;
            int gk = kt_ * 64 + row;
            cp_async16(Ks + (buf * 64 + row) * 72 + sg * 8,
                       qb + (long long)gk * 2304 + 64 + sg * 8, gk < Sc ? 16 : 0);
        }
#pragma unroll
        for (int i = 0; i < 2; i++) {
            int idx = t + i * 256;
            int row = idx >> 3, sg = idx & 7;
            int gk = kt_ * 64 + row;
            cp_async16(Vs + (buf * 64 + row) * 72 + sg * 8,
                       qb + (long long)gk * 2304 + 128 + sg * 8, gk < Sc ? 16 : 0);
        }
    };
    const int nt = (Sc + 63) / 64;   // 10
    issueKV(0, 0);
    asm volatile("cp.async.commit_group;\n");
    issueKV(1, 1);
    asm volatile("cp.async.commit_group;\n");

    float accO[8][4] = {};
    float mr0 = -1e30f, mr1 = -1e30f, lr0 = 0.f, lr1 = 0.f;
    __half* Pw = Ps + w * 16 * 72;
    const __half* Qw = Qs + w * 16 * 72;

    int arow = lane & 15;
    int acof = (lane >> 4) << 3;
    int brow = ((lane >> 4) << 3) + (lane & 7);
    int bcof = ((lane >> 3) & 1) << 3;

    // Q + KV0 ready (1 group pending), hoist Q fragments to registers
    asm volatile("cp.async.wait_group 1;\n");
    __syncthreads();
    uint32_t afq[4][4];
#pragma unroll
    for (int ks = 0; ks < 4; ks++)
        ldsm4h(afq[ks], Qw + arow * 72 + ks * 16 + acof);

    for (int kt_ = 0; kt_ < nt; kt_++) {
        int buf = kt_ % 3;
        asm volatile("cp.async.wait_group 1;\n");
        __syncthreads();
        if (kt_ + 2 < nt) issueKV(kt_ + 2, (kt_ + 2) % 3);
        asm volatile("cp.async.commit_group;\n");

        float s[8][4] = {};
        const __half* Kb = Ks + buf * 64 * 72;
#pragma unroll
        for (int ks = 0; ks < 4; ks++) {
            int kc = ks * 16;
#pragma unroll
            for (int nb = 0; nb < 4; nb++) {
                uint32_t bq[4];
                ldsm4h(bq, Kb + (nb * 16 + brow) * 72 + kc + bcof);
#pragma unroll
                for (int blk = 0; blk < 2; blk++) {
                    uint32_t b2[2] = { bq[blk * 2], bq[blk * 2 + 1] };
                    mma_f16(s[nb * 2 + blk], afq[ks], b2);
                }
            }
        }
        float rm0 = -1e30f, rm1 = -1e30f;
#pragma unroll
        for (int nf = 0; nf < 8; nf++) {
#pragma unroll
            for (int cc = 0; cc < 4; cc++) {
                int col = kt_ * 64 + nf * 8 + tig * 2 + (cc & 1);
                float v = s[nf][cc] * 0.125f;
                v = (col < Sc) ? v : -1e30f;
                s[nf][cc] = v;
                if (cc < 2) rm0 = fmaxf(rm0, v); else rm1 = fmaxf(rm1, v);
            }
        }
        rm0 = fmaxf(rm0, __shfl_xor_sync(0xffffffffu, rm0, 1));
        rm0 = fmaxf(rm0, __shfl_xor_sync(0xffffffffu, rm0, 2));
        rm1 = fmaxf(rm1, __shfl_xor_sync(0xffffffffu, rm1, 1));
        rm1 = fmaxf(rm1, __shfl_xor_sync(0xffffffffu, rm1, 2));
        float nm0 = fmaxf(mr0, rm0), nm1 = fmaxf(mr1, rm1);
        float cor0 = __expf(mr0 - nm0), cor1 = __expf(mr1 - nm1);
        float rs0 = 0.f, rs1 = 0.f;
#pragma unroll
        for (int nf = 0; nf < 8; nf++) {
            int colb = nf * 8 + tig * 2;
            float p0 = __expf(s[nf][0] - nm0);
            float p1 = __expf(s[nf][1] - nm0);
            float p2 = __expf(s[nf][2] - nm1);
            float p3 = __expf(s[nf][3] - nm1);
            rs0 += p0 + p1; rs1 += p2 + p3;
            Pw[g * 72 + colb]           = __float2half(p0);
            Pw[g * 72 + colb + 1]       = __float2half(p1);
            Pw[(g + 8) * 72 + colb]     = __float2half(p2);
            Pw[(g + 8) * 72 + colb + 1] = __float2half(p3);
        }
        rs0 += __shfl_xor_sync(0xffffffffu, rs0, 1);
        rs0 += __shfl_xor_sync(0xffffffffu, rs0, 2);
        rs1 += __shfl_xor_sync(0xffffffffu, rs1, 1);
        rs1 += __shfl_xor_sync(0xffffffffu, rs1, 2);
        lr0 = lr0 * cor0 + rs0;
        lr1 = lr1 * cor1 + rs1;
        mr0 = nm0; mr1 = nm1;
#pragma unroll
        for (int nf = 0; nf < 8; nf++) {
            accO[nf][0] *= cor0; accO[nf][1] *= cor0;
            accO[nf][2] *= cor1; accO[nf][3] *= cor1;
        }
        __syncwarp();
        const __half* Vb = Vs + buf * 64 * 72;
#pragma unroll
        for (int ks = 0; ks < 4; ks++) {
            int kc = ks * 16;
            uint32_t af[4];
            ldsm4h(af, Pw + arow * 72 + kc + acof);
#pragma unroll
            for (int nb = 0; nb < 4; nb++) {
                uint32_t vq[4];
                ldsm4h_trans(vq, Vb + (kc + brow) * 72 + nb * 16 + bcof);
#pragma unroll
                for (int blk = 0; blk < 2; blk++) {
                    uint32_t b2[2] = { vq[blk], vq[blk + 2] };
                    mma_f16(accO[nb * 2 + blk], af, b2);
                }
            }
        }
        __syncwarp();
    }

    float inv0 = 1.0f / lr0, inv1 = 1.0f / lr1;
    int r0 = qt * 128 + w * 16 + g;
    int r1 = r0 + 8;
#pragma unroll
    for (int nf = 0; nf < 8; nf++) {
        int colb = nf * 8 + tig * 2;
        if (r0 < Sc)
            *(__half2*)(om2 + ((long long)b * Sc + r0) * Dc + h * 64 + colb) =
                __floats2half2_rn(accO[nf][0] * inv0, accO[nf][1] * inv0);
        if (r1 < Sc)
            *(__half2*)(om2 + ((long long)b * Sc + r1) * Dc + h * 64 + colb) =
                __floats2half2_rn(accO[nf][2] * inv1, accO[nf][3] * inv1);
    }
}

// ---------------- producers / prep ----------------
__global__ void im2col_kernel(const float* __restrict__ x, __half* __restrict__ col) {
    long long idx = (long long)blockIdx.x * blockDim.x + threadIdx.x;
    long long total = (long long)Bc * NP * Dc;
    if (idx >= total) return;
    int k = (int)(idx % Dc);
    int rem = (int)(idx / Dc);
    int p = rem % NP;
    int b = rem / NP;
    int ph = p / GRID24, pw = p % GRID24;
    int ci = k / 256, k2 = k % 256;
    int kh = k2 / 16, kw = k2 % 16;
    col[idx] = __float2half(x[(((long long)b * 3 + ci) * IMGc + ph * 16 + kh) * IMGc + pw * 16 + kw]);
}

__global__ void transpose_wqkv_kernel(const float* __restrict__ w, __half* __restrict__ wt) {
    long long idx = (long long)blockIdx.x * blockDim.x + threadIdx.x;
    long long total = (long long)Lc * 3 * Dc * Dc;
    if (idx >= total) return;
    int d = (int)(idx % Dc);
    int rem = (int)(idx / Dc);
    int n = rem % (3 * Dc);
    int l = rem / (3 * Dc);
    int h = n / 192, e = n % 192;
    wt[idx] = __float2half(w[(((long long)l * Hc + h) * Dc + d) * 192 + e]);
}

__device__ __forceinline__ void btrans_tile(const float* inl, __half* outl,
                                            int R, int Cn, int ct, int rt,
                                            int tx, int ty, float tile[32][33]) {
#pragma unroll
    for (int j = 0; j < 4; j++) {
        int r = rt * 32 + ty + j * 8;
        int c = ct * 32 + tx;
        tile[ty + j * 8][tx] = (r < R && c < Cn) ? inl[(long long)r * Cn + c] : 0.f;
    }
    __syncthreads();
#pragma unroll
    for (int j = 0; j < 4; j++) {
        int c = ct * 32 + ty + j * 8;
        int r = rt * 32 + tx;
        if (c < Cn && r < R)
            outl[(long long)c * R + r] = __float2half(tile[tx][ty + j * 8]);
    }
}

static const int NT_WM = 24 * 24 * Lc;
static const int NT_W1 = 96 * 24 * Lc;
static const int NT_W2 = 24 * 96 * Lc;

__global__ void btrans_multi_kernel(const float* __restrict__ wmsa, __half* __restrict__ wm2,
                                    const float* __restrict__ w1, __half* __restrict__ w12,
                                    const float* __restrict__ w2, __half* __restrict__ w22) {
    __shared__ float tile[32][33];
    int bx = blockIdx.x;
    int tx = threadIdx.x, ty = threadIdx.y;
    if (bx < NT_WM) {
        int l = bx / (24 * 24), rem = bx % (24 * 24);
        int rt = rem / 24, ct = rem % 24;
        btrans_tile(wmsa + (long long)l * Dc * Dc, wm2 + (long long)l * Dc * Dc,
                    Dc, Dc, ct, rt, tx, ty, tile);
    } else if (bx < NT_WM + NT_W1) {
        int b2 = bx - NT_WM;
        int l = b2 / (96 * 24), rem = b2 % (96 * 24);
        int rt = rem / 96, ct = rem % 96;
        btrans_tile(w1 + (long long)l * Dc * Mc, w12 + (long long)l * Dc * Mc,
                    Dc, Mc, ct, rt, tx, ty, tile);
    } else {
        int b2 = bx - NT_WM - NT_W1;
        int l = b2 / (24 * 96), rem = b2 % (24 * 96);
        int rt = rem / 24, ct = rem % 24;
        btrans_tile(w2 + (long long)l * Mc * Dc, w22 + (long long)l * Mc * Dc,
                    Mc, Dc, ct, rt, tx, ty, tile);
    }
}

__global__ void btrans_h_kernel(const float* __restrict__ in, __half* __restrict__ out,
                                int R, int Cn) {
    __shared__ float tile[32][33];
    btrans_tile(in, out, R, Cn, blockIdx.x, blockIdx.y, threadIdx.x, threadIdx.y, tile);
}

__global__ void hcopy_kernel(const float* __restrict__ w, __half* __restrict__ o, long long n) {
    long long i = (long long)blockIdx.x * blockDim.x + threadIdx.x;
    if (i < n) o[i] = __float2half(w[i]);
}

__global__ void embed_kernel(const float* __restrict__ pout, const float* __restrict__ cls,
                             const float* __restrict__ pos, float* __restrict__ t) {
    long long idx = (long long)blockIdx.x * blockDim.x + threadIdx.x;
    long long total = (long long)Bc * Sc * Dc;
    if (idx >= total) return;
    int j = (int)(idx % Dc);
    int rem = (int)(idx / Dc);
    int r = rem % Sc;
    int b = rem / Sc;
    float v;
    if (r == 0) {
        v = cls[j];
    } else {
        int i = (r - 1) * Dc + j;
        int c = i / NP, p = i % NP;
        v = pout[((long long)b * NP + p) * Dc + c];
    }
    t[idx] = v + pos[r * Dc + j];
}

// single LN -> fp16 only
__global__ void layernorm_kernel(const float* __restrict__ x, const float* __restrict__ g,
                                 const float* __restrict__ b, __half* __restrict__ y2, int rows) {
    __shared__ float red[256];
    int row = blockIdx.x;
    if (row >= rows) return;
    int t = threadIdx.x;
    const float* xr = x + (long long)row * Dc;
    float v[3];
    float s = 0.f;
#pragma unroll
    for (int i = 0; i < 3; i++) { v[i] = xr[t + i * 256]; s += v[i]; }
    red[t] = s; __syncthreads();
    for (int o = 128; o > 0; o >>= 1) { if (t < o) red[t] += red[t + o]; __syncthreads(); }
    float mu = red[0] / Dc;
    __syncthreads();
    float s2 = 0.f;
#pragma unroll
    for (int i = 0; i < 3; i++) { float d = v[i] - mu; s2 += d * d; }
    red[t] = s2; __syncthreads();
    for (int o = 128; o > 0; o >>= 1) { if (t < o) red[t] += red[t + o]; __syncthreads(); }
    float rstd = rsqrtf(red[0] / Dc + 1e-5f);
#pragma unroll
    for (int i = 0; i < 3; i++) {
        int j = t + i * 256;
        y2[(long long)row * Dc + j] = __float2half((v[i] - mu) * rstd * g[j] + b[j]);
    }
}

// final LN over cls rows gathered from t (row stride Sc*Dc)
__global__ void layernorm_cls_kernel(const float* __restrict__ tfull,
                                     const float* __restrict__ g, const float* __restrict__ b,
                                     __half* __restrict__ y2, int rows) {
    __shared__ float red[256];
    int row = blockIdx.x;
    if (row >= rows) return;
    int t = threadIdx.x;
    const float* xr = tfull + (long long)row * Sc * Dc;
    float v[3];
    float s = 0.f;
#pragma unroll
    for (int i = 0; i < 3; i++) { v[i] = xr[t + i * 256]; s += v[i]; }
    red[t] = s; __syncthreads();
    for (int o = 128; o > 0; o >>= 1) { if (t < o) red[t] += red[t + o]; __syncthreads(); }
    float mu = red[0] / Dc;
    __syncthreads();
    float s2 = 0.f;
#pragma unroll
    for (int i = 0; i < 3; i++) { float d = v[i] - mu; s2 += d * d; }
    red[t] = s2; __syncthreads();
    for (int o = 128; o > 0; o >>= 1) { if (t < o) red[t] += red[t + o]; __syncthreads(); }
    float rstd = rsqrtf(red[0] / Dc + 1e-5f);
#pragma unroll
    for (int i = 0; i < 3; i++) {
        int j = t + i * 256;
        y2[(long long)row * Dc + j] = __float2half((v[i] - mu) * rstd * g[j] + b[j]);
    }
}

__global__ void layernorm2_kernel(const float* __restrict__ x,
                                  const float* __restrict__ g1, const float* __restrict__ b1,
                                  const float* __restrict__ g2, const float* __restrict__ b2,
                                  __half* __restrict__ y2, int rows) {
    __shared__ float red[256];
    int row = blockIdx.x;
    if (row >= rows) return;
    int t = threadIdx.x;
    const float* xr = x + (long long)row * Dc;
    float v[3];
    float s = 0.f;
#pragma unroll
    for (int i = 0; i < 3; i++) { v[i] = xr[t + i * 256]; s += v[i]; }
    red[t] = s; __syncthreads();
    for (int o = 128; o > 0; o >>= 1) { if (t < o) red[t] += red[t + o]; __syncthreads(); }
    float mu = red[0] / Dc;
    __syncthreads();
    float s2 = 0.f;
#pragma unroll
    for (int i = 0; i < 3; i++) { float d = v[i] - mu; s2 += d * d; }
    red[t] = s2; __syncthreads();
    for (int o = 128; o > 0; o >>= 1) { if (t < o) red[t] += red[t + o]; __syncthreads(); }
    float rstd = rsqrtf(red[0] / Dc + 1e-5f);
    __syncthreads();
    s = 0.f;
#pragma unroll
    for (int i = 0; i < 3; i++) {
        int j = t + i * 256;
        v[i] = (v[i] - mu) * rstd * g1[j] + b1[j];
        s += v[i];
    }
    red[t] = s; __syncthreads();
    for (int o = 128; o > 0; o >>= 1) { if (t < o) red[t] += red[t + o]; __syncthreads(); }
    mu = red[0] / Dc;
    __syncthreads();
    s2 = 0.f;
#pragma unroll
    for (int i = 0; i < 3; i++) { float d = v[i] - mu; s2 += d * d; }
    red[t] = s2; __syncthreads();
    for (int o = 128; o > 0; o >>= 1) { if (t < o) red[t] += red[t + o]; __syncthreads(); }
    rstd = rsqrtf(red[0] / Dc + 1e-5f);
#pragma unroll
    for (int i = 0; i < 3; i++) {
        int j = t + i * 256;
        y2[(long long)row * Dc + j] = __float2half((v[i] - mu) * rstd * g2[j] + b2[j]);
    }
}

__global__ void softmax_kernel(float* __restrict__ x, long long rows, int n) {
    __shared__ float red[256];
    long long row = blockIdx.x;
    if (row >= rows) return;
    int t = threadIdx.x;
    float* xr = x + row * n;
    float lmax = -1e30f;
    for (int j = t; j < n; j += 256) lmax = fmaxf(lmax, xr[j]);
    red[t] = lmax; __syncthreads();
    for (int o = 128; o > 0; o >>= 1) { if (t < o) red[t] = fmaxf(red[t], red[t + o]); __syncthreads(); }
    float mx = red[0];
    __syncthreads();
    float ls = 0.f;
    for (int j = t; j < n; j += 256) { float e = expf(xr[j] - mx); xr[j] = e; ls += e; }
    red[t] = ls; __syncthreads();
    for (int o = 128; o > 0; o >>= 1) { if (t < o) red[t] += red[t + o]; __syncthreads(); }
    float inv = 1.0f / red[0];
    for (int j = t; j < n; j += 256) xr[j] *= inv;
}

// ---------------- host helpers ----------------
static void run_hgemm(const __half* A, const __half* Bm, const float* bias,
                      const float* res, const __half* res2,
                      float* Cf, __half* C2, int M, int N, int K,
                      int ldc, int act) {
    dim3 grid((N + 127) / 128, (M + 127) / 128, 1);
    hgemm_kernel<<<grid, 256, GEMM_SMEM>>>(A, Bm, bias, res, res2, Cf, C2, M, N, K, ldc, act);
}

extern "C" void kernel_launch(void* const* d_in, const int* in_sizes, int n_in,
                              void* d_out, int out_size) {
    const float* x       = (const float*)d_in[0];
    const float* conv_w  = (const float*)d_in[1];
    const float* conv_b  = (const float*)d_in[2];
    const float* cls_tok = (const float*)d_in[3];
    const float* pos_emb = (const float*)d_in[4];
    const float* ln1_g   = (const float*)d_in[5];
    const float* ln1_b   = (const float*)d_in[6];
    const float* wqkv    = (const float*)d_in[7];
    const float* bqkv    = (const float*)d_in[8];
    const float* wmsa    = (const float*)d_in[9];
    const float* bmsa    = (const float*)d_in[10];
    const float* ln2_g   = (const float*)d_in[11];
    const float* ln2_b   = (const float*)d_in[12];
    const float* lnm_g   = (const float*)d_in[13];
    const float* lnm_b   = (const float*)d_in[14];
    const float* w1      = (const float*)d_in[15];
    const float* b1      = (const float*)d_in[16];
    const float* w2      = (const float*)d_in[17];
    const float* b2      = (const float*)d_in[18];
    const float* lnf_g   = (const float*)d_in[19];
    const float* lnf_b   = (const float*)d_in[20];
    const float* whead   = (const float*)d_in[21];
    const float* bhead   = (const float*)d_in[22];
    float* out = (float*)d_out;

    float *t_, *h_;
    __half *h2_, *om2_, *mb2_, *qkv2_, *col2_, *cls2_, *wq2_, *cw2_, *wm2_, *w12_, *w22_, *wh2_;
    cudaGetSymbolAddress((void**)&t_,  g_t);
    cudaGetSymbolAddress((void**)&h_,  g_h);
    cudaGetSymbolAddress((void**)&h2_, g_h2);
    cudaGetSymbolAddress((void**)&om2_, g_om2);
    cudaGetSymbolAddress((void**)&mb2_, g_mb2);
    cudaGetSymbolAddress((void**)&qkv2_, g_qkv2);
    cudaGetSymbolAddress((void**)&col2_, g_col2);
    cudaGetSymbolAddress((void**)&cls2_, g_cls2);
    cudaGetSymbolAddress((void**)&wq2_, g_wq2);
    cudaGetSymbolAddress((void**)&cw2_, g_cw2);
    cudaGetSymbolAddress((void**)&wm2_, g_wm2);
    cudaGetSymbolAddress((void**)&w12_, g_w12);
    cudaGetSymbolAddress((void**)&w22_, g_w22);
    cudaGetSymbolAddress((void**)&wh2_, g_wh2);

    cudaFuncSetAttribute(flash_kernel, cudaFuncAttributeMaxDynamicSharedMemorySize, FLASH_SMEM);
    cudaFuncSetAttribute(hgemm_kernel, cudaFuncAttributeMaxDynamicSharedMemorySize, GEMM_SMEM);

    // --- prep ---
    hcopy_kernel<<<(Dc * Dc + 255) / 256, 256>>>(conv_w, cw2_, (long long)Dc * Dc);
    {
        long long tot = (long long)Lc * 3 * Dc * Dc;
        transpose_wqkv_kernel<<<(int)((tot + 255) / 256), 256>>>(wqkv, wq2_);
    }
    btrans_multi_kernel<<<NT_WM + NT_W1 + NT_W2, dim3(32, 8)>>>(wmsa, wm2_, w1, w12_,
                                                                w2, w22_);
    btrans_h_kernel<<<dim3((NCc + 31) / 32, Dc / 32), dim3(32, 8)>>>(whead, wh2_, Dc, NCc);
    {
        long long tot = (long long)Bc * NP * Dc;
        im2col_kernel<<<(int)((tot + 255) / 256), 256>>>(x, col2_);
    }
    run_hgemm(col2_, cw2_, conv_b, nullptr, nullptr, h_, nullptr, Bc * NP, Dc, Dc, Dc, 0);
    {
        long long tot = (long long)Bc * Sc * Dc;
        embed_kernel<<<(int)((tot + 255) / 256), 256>>>(h_, cls_tok, pos_emb, t_);
    }

    // --- encoder layers ---
    for (int l = 0; l < Lc; l++) {
        // ln1 -> h2 (fp16 only; also serves as the MSA residual)
        layernorm_kernel<<<BS, 256>>>(t_, ln1_g + l * Dc, ln1_b + l * Dc, h2_, BS);
        run_hgemm(h2_, wq2_ + (long long)l * 3 * Dc * Dc, bqkv + l * 3 * Dc, nullptr, nullptr,
                  nullptr, qkv2_, BS, 3 * Dc, Dc, 3 * Dc, 0);
        flash_kernel<<<dim3((Sc + 127) / 128, Hc, Bc), 256, FLASH_SMEM>>>(qkv2_, om2_);
        // msa: t = om2 @ wm2 + bmsa + h2 (fp16 residual)
        run_hgemm(om2_, wm2_ + (long long)l * Dc * Dc, bmsa + l * Dc, nullptr, h2_,
                  t_, nullptr, BS, Dc, Dc, Dc, 0);
        layernorm2_kernel<<<BS, 256>>>(t_, ln2_g + l * Dc, ln2_b + l * Dc,
                                       lnm_g + l * Dc, lnm_b + l * Dc, h2_, BS);
        run_hgemm(h2_, w12_ + (long long)l * Mc * Dc, b1 + l * Mc, nullptr, nullptr,
                  nullptr, mb2_, BS, Mc, Dc, Mc, 1);
        run_hgemm(mb2_, w22_ + (long long)l * Dc * Mc, b2 + l * Dc, t_, nullptr,
                  t_, nullptr, BS, Dc, Mc, Dc, 0);
    }

    // --- head ---
    layernorm_cls_kernel<<<Bc, 256>>>(t_, lnf_g, lnf_b, cls2_, Bc);
    run_hgemm(cls2_, wh2_, bhead, nullptr, nullptr, out, nullptr, Bc, NCc, Dc, NCc, 0);
    softmax_kernel<<<Bc, 256>>>(out, Bc, NCc);
}

// round 15
// speedup vs baseline: 1.0699x; 1.0699x over previous
#include <cuda_runtime.h>
#include <cuda_fp16.h>
#include <math.h>
#include <stdint.h>

// ---------------- dims ----------------
static const int Lc = 12, Hc = 12, Dc = 768, HDc = 64, Mc = 3072;
static const int IMGc = 384, Bc = 32, NCc = 1000;
static const int NP = 576;
static const int Sc = 577;
static const int BS = Bc * Sc;        // 18464
static const int GRID24 = 24;
static const int GS = 5;              // gemm pipeline stages

// ---------------- scratch ----------------
__device__ float g_t[BS * Dc];                 // residual (fp32)
__device__ float g_h[BS * Dc];                 // patchify gemm out (fp32)
// fp16 operands
__device__ __half g_h2[BS * Dc];
__device__ __half g_om2[BS * Dc];
__device__ __half g_mb2[(long long)BS * Mc];
__device__ __half g_qkv2[(long long)BS * 3 * Dc];
__device__ __half g_col2[Bc * NP * Dc];
__device__ __half g_cls2[Bc * Dc];
__device__ __half g_wq2[(long long)Lc * 3 * Dc * Dc];  // [l][n=2304][k=768]
__device__ __half g_cw2[Dc * Dc];                      // [n][k]
__device__ __half g_wm2[(long long)Lc * Dc * Dc];
__device__ __half g_w12[(long long)Lc * Mc * Dc];
__device__ __half g_w22[(long long)Lc * Dc * Mc];
__device__ __half g_wh2[NCc * Dc];

// ---------------- helpers ----------------
__device__ __forceinline__ void mma_f16(float c[4], const uint32_t a[4], const uint32_t b[2]) {
    asm volatile(
        "mma.sync.aligned.m16n8k16.row.col.f32.f16.f16.f32 "
        "{%0,%1,%2,%3}, {%4,%5,%6,%7}, {%8,%9}, {%0,%1,%2,%3};\n"
        : "+f"(c[0]), "+f"(c[1]), "+f"(c[2]), "+f"(c[3])
        : "r"(a[0]), "r"(a[1]), "r"(a[2]), "r"(a[3]), "r"(b[0]), "r"(b[1]));
}

__device__ __forceinline__ void cp_async16(void* smem_dst, const void* gsrc, int sz) {
    unsigned sm = (unsigned)__cvta_generic_to_shared(smem_dst);
    asm volatile("cp.async.cg.shared.global [%0], [%1], 16, %2;\n" :: "r"(sm), "l"(gsrc), "r"(sz));
}

__device__ __forceinline__ void ldsm4h(uint32_t r[4], const __half* p) {
    unsigned a = (unsigned)__cvta_generic_to_shared(p);
    asm volatile("ldmatrix.sync.aligned.m8n8.x4.shared.b16 {%0,%1,%2,%3}, [%4];\n"
                 : "=r"(r[0]), "=r"(r[1]), "=r"(r[2]), "=r"(r[3]) : "r"(a));
}
__device__ __forceinline__ void ldsm4h_trans(uint32_t r[4], const __half* p) {
    unsigned a = (unsigned)__cvta_generic_to_shared(p);
    asm volatile("ldmatrix.sync.aligned.m8n8.x4.trans.shared.b16 {%0,%1,%2,%3}, [%4];\n"
                 : "=r"(r[0]), "=r"(r[1]), "=r"(r[2]), "=r"(r[3]) : "r"(a));
}

// ---------------- fp16 tensor GEMM (R10 shape, GS=5) ----------------
static const int HROW = 40;
static const int HSTG = 128 * HROW;
static const int GEMM_SMEM = GS * 2 * HSTG * 2;  // 102400 bytes

__global__ void __launch_bounds__(256, 2)
hgemm_kernel(const __half* __restrict__ A, const __half* __restrict__ Bm,
             const float* __restrict__ bias, const float* __restrict__ res,
             const __half* __restrict__ res2,
             float* __restrict__ Cf, __half* __restrict__ C2,
             int M, int N, int K, int ldc, int act) {
    extern __shared__ __half smh[];

    int t = threadIdx.x;
    int lane = t & 31, wid = t >> 5;
    int wm = wid >> 2, wn = wid & 3;
    int g = lane >> 2, tig = lane & 3;
    int m0 = blockIdx.y * 128, n0 = blockIdx.x * 128;

    float acc[4][4][4] = {};
    int nk = K / 32;

    auto loadTile = [&](int k0, int s) {
        __half* dstA = smh + s * 2 * HSTG;
        __half* dstB = dstA + HSTG;
#pragma unroll
        for (int i = 0; i < 2; i++) {
            int c = t + i * 256;
            int r = c >> 2, sg = (c & 3) * 8;
            cp_async16(dstA + r * HROW + sg, A + (long long)(m0 + r) * K + k0 + sg,
                       (m0 + r < M) ? 16 : 0);
        }
#pragma unroll
        for (int i = 0; i < 2; i++) {
            int c = t + i * 256;
            int r = c >> 2, sg = (c & 3) * 8;
            cp_async16(dstB + r * HROW + sg, Bm + (long long)(n0 + r) * K + k0 + sg,
                       (n0 + r < N) ? 16 : 0);
        }
    };

#pragma unroll
    for (int s = 0; s < GS - 1; s++) {
        loadTile(s * 32, s);
        asm volatile("cp.async.commit_group;\n");
    }

    int a_row = wm * 64 + (lane & 15);
    int a_cofs = (lane >> 4) << 3;
    int b_row = wn * 32 + ((lane >> 4) << 3) + (lane & 7);
    int b_cofs = ((lane >> 3) & 1) << 3;

    for (int it = 0; it < nk; it++) {
        asm volatile("cp.async.wait_group %0;\n" :: "n"(GS - 2));
        __syncthreads();
        if (it + GS - 1 < nk) loadTile((it + GS - 1) * 32, (it + GS - 1) % GS);
        asm volatile("cp.async.commit_group;\n");

        const __half* Ab = smh + (it % GS) * 2 * HSTG;
        const __half* Bb = Ab + HSTG;
#pragma unroll
        for (int ks = 0; ks < 2; ks++) {
            int kc = ks * 16;
            uint32_t af[4][4], bq[2][4];
#pragma unroll
            for (int mt = 0; mt < 4; mt++)
                ldsm4h(af[mt], Ab + (a_row + mt * 16) * HROW + kc + a_cofs);
#pragma unroll
            for (int nb = 0; nb < 2; nb++)
                ldsm4h(bq[nb], Bb + (b_row + nb * 16) * HROW + kc + b_cofs);
#pragma unroll
            for (int mt = 0; mt < 4; mt++)
#pragma unroll
                for (int nt = 0; nt < 4; nt++) {
                    uint32_t b2[2] = { bq[nt >> 1][(nt & 1) * 2], bq[nt >> 1][(nt & 1) * 2 + 1] };
                    mma_f16(acc[mt][nt], af[mt], b2);
                }
        }
    }

    // epilogue: vectorized (col, col+1) pair stores
#pragma unroll
    for (int mt = 0; mt < 4; mt++) {
#pragma unroll
        for (int nt = 0; nt < 4; nt++) {
            int row = m0 + wm * 64 + mt * 16 + g;
            int col = n0 + wn * 32 + nt * 8 + tig * 2;
            if (col >= N) continue;
            int pair = (col + 1 < N);
#pragma unroll
            for (int hp = 0; hp < 2; hp++) {
                int m = row + hp * 8;
                if (m >= M) continue;
                float v0 = acc[mt][nt][hp * 2];
                float v1 = acc[mt][nt][hp * 2 + 1];
                if (bias) { v0 += bias[col]; if (pair) v1 += bias[col + 1]; }
                if (res) {
                    v0 += res[(long long)m * ldc + col];
                    if (pair) v1 += res[(long long)m * ldc + col + 1];
                }
                if (res2) {
                    if (pair) {
                        __half2 r2 = *(const __half2*)(res2 + (long long)m * ldc + col);
                        v0 += __low2float(r2);
                        v1 += __high2float(r2);
                    } else {
                        v0 += __half2float(res2[(long long)m * ldc + col]);
                    }
                }
                if (act == 1) {
                    v0 = 0.5f * v0 * (1.0f + erff(v0 * 0.7071067811865476f));
                    v1 = 0.5f * v1 * (1.0f + erff(v1 * 0.7071067811865476f));
                }
                if (Cf) {
                    if (pair)
                        *(float2*)(Cf + (long long)m * ldc + col) = make_float2(v0, v1);
                    else
                        Cf[(long long)m * ldc + col] = v0;
                }
                if (C2) {
                    if (pair)
                        *(__half2*)(C2 + (long long)m * ldc + col) = __floats2half2_rn(v0, v1);
                    else
                        C2[(long long)m * ldc + col] = __float2half(v0);
                }
            }
        }
    }
}

// ---------------- fp16 flash attention: 3-stage K/V pipeline, Q frags hoisted ----------------
static const int FLASH_SMEM = (9216 + 9216 + 13824 + 13824) * 2;   // 92160 B

__global__ void __launch_bounds__(256, 2)
flash_kernel(const __half* __restrict__ qkv, __half* __restrict__ om2) {
    extern __shared__ __half smh[];
    __half* Qs = smh;               // [128][72]
    __half* Ps = smh + 9216;        // [8][16][72]
    __half* Ks = smh + 18432;       // [3][64][72]
    __half* Vs = smh + 32256;       // [3][64][72]

    int qt = blockIdx.x, h = blockIdx.y, b = blockIdx.z;
    int t = threadIdx.x, lane = t & 31, w = t >> 5, g = lane >> 2, tig = lane & 3;
    const __half* qb = qkv + (long long)b * Sc * 2304 + h * 192;

#pragma unroll
    for (int i = 0; i < 4; i++) {
        int idx = t + i * 256;
        int row = idx >> 3, sg = idx & 7;
        int gr = qt * 128 + row;
        cp_async16(Qs + row * 72 + sg * 8, qb + (long long)gr * 2304 + sg * 8, gr < Sc ? 16 : 0);
    }
    auto issueKV = [&](int kt_, int buf) {
#pragma unroll
        for (int i = 0; i < 2; i++) {
            int idx = t + i * 256;
            int row = idx >> 3, sg = idx & 7;
            int gk = kt_ * 64 + row;
            cp_async16(Ks + (buf * 64 + row) * 72 + sg * 8,
                       qb + (long long)gk * 2304 + 64 + sg * 8, gk < Sc ? 16 : 0);
        }
#pragma unroll
        for (int i = 0; i < 2; i++) {
            int idx = t + i * 256;
            int row = idx >> 3, sg = idx & 7;
            int gk = kt_ * 64 + row;
            cp_async16(Vs + (buf * 64 + row) * 72 + sg * 8,
                       qb + (long long)gk * 2304 + 128 + sg * 8, gk < Sc ? 16 : 0);
        }
    };
    const int nt = (Sc + 63) / 64;   // 10
    issueKV(0, 0);
    asm volatile("cp.async.commit_group;\n");
    issueKV(1, 1);
    asm volatile("cp.async.commit_group;\n");

    float accO[8][4] = {};
    float mr0 = -1e30f, mr1 = -1e30f, lr0 = 0.f, lr1 = 0.f;
    __half* Pw = Ps + w * 16 * 72;
    const __half* Qw = Qs + w * 16 * 72;

    int arow = lane & 15;
    int acof = (lane >> 4) << 3;
    int brow = ((lane >> 4) << 3) + (lane & 7);
    int bcof = ((lane >> 3) & 1) << 3;

    asm volatile("cp.async.wait_group 1;\n");
    __syncthreads();
    uint32_t afq[4][4];
#pragma unroll
    for (int ks = 0; ks < 4; ks++)
        ldsm4h(afq[ks], Qw + arow * 72 + ks * 16 + acof);

    for (int kt_ = 0; kt_ < nt; kt_++) {
        int buf = kt_ % 3;
        asm volatile("cp.async.wait_group 1;\n");
        __syncthreads();
        if (kt_ + 2 < nt) issueKV(kt_ + 2, (kt_ + 2) % 3);
        asm volatile("cp.async.commit_group;\n");

        float s[8][4] = {};
        const __half* Kb = Ks + buf * 64 * 72;
#pragma unroll
        for (int ks = 0; ks < 4; ks++) {
            int kc = ks * 16;
#pragma unroll
            for (int nb = 0; nb < 4; nb++) {
                uint32_t bq[4];
                ldsm4h(bq, Kb + (nb * 16 + brow) * 72 + kc + bcof);
#pragma unroll
                for (int blk = 0; blk < 2; blk++) {
                    uint32_t b2[2] = { bq[blk * 2], bq[blk * 2 + 1] };
                    mma_f16(s[nb * 2 + blk], afq[ks], b2);
                }
            }
        }
        float rm0 = -1e30f, rm1 = -1e30f;
#pragma unroll
        for (int nf = 0; nf < 8; nf++) {
#pragma unroll
            for (int cc = 0; cc < 4; cc++) {
                int col = kt_ * 64 + nf * 8 + tig * 2 + (cc & 1);
                float v = s[nf][cc] * 0.125f;
                v = (col < Sc) ? v : -1e30f;
                s[nf][cc] = v;
                if (cc < 2) rm0 = fmaxf(rm0, v); else rm1 = fmaxf(rm1, v);
            }
        }
        rm0 = fmaxf(rm0, __shfl_xor_sync(0xffffffffu, rm0, 1));
        rm0 = fmaxf(rm0, __shfl_xor_sync(0xffffffffu, rm0, 2));
        rm1 = fmaxf(rm1, __shfl_xor_sync(0xffffffffu, rm1, 1));
        rm1 = fmaxf(rm1, __shfl_xor_sync(0xffffffffu, rm1, 2));
        float nm0 = fmaxf(mr0, rm0), nm1 = fmaxf(mr1, rm1);
        float cor0 = __expf(mr0 - nm0), cor1 = __expf(mr1 - nm1);
        float rs0 = 0.f, rs1 = 0.f;
#pragma unroll
        for (int nf = 0; nf < 8; nf++) {
            int colb = nf * 8 + tig * 2;
            float p0 = __expf(s[nf][0] - nm0);
            float p1 = __expf(s[nf][1] - nm0);
            float p2 = __expf(s[nf][2] - nm1);
            float p3 = __expf(s[nf][3] - nm1);
            rs0 += p0 + p1; rs1 += p2 + p3;
            *(__half2*)(Pw + g * 72 + colb)       = __floats2half2_rn(p0, p1);
            *(__half2*)(Pw + (g + 8) * 72 + colb) = __floats2half2_rn(p2, p3);
        }
        rs0 += __shfl_xor_sync(0xffffffffu, rs0, 1);
        rs0 += __shfl_xor_sync(0xffffffffu, rs0, 2);
        rs1 += __shfl_xor_sync(0xffffffffu, rs1, 1);
        rs1 += __shfl_xor_sync(0xffffffffu, rs1, 2);
        lr0 = lr0 * cor0 + rs0;
        lr1 = lr1 * cor1 + rs1;
        mr0 = nm0; mr1 = nm1;
#pragma unroll
        for (int nf = 0; nf < 8; nf++) {
            accO[nf][0] *= cor0; accO[nf][1] *= cor0;
            accO[nf][2] *= cor1; accO[nf][3] *= cor1;
        }
        __syncwarp();
        const __half* Vb = Vs + buf * 64 * 72;
#pragma unroll
        for (int ks = 0; ks < 4; ks++) {
            int kc = ks * 16;
            uint32_t af[4];
            ldsm4h(af, Pw + arow * 72 + kc + acof);
#pragma unroll
            for (int nb = 0; nb < 4; nb++) {
                uint32_t vq[4];
                ldsm4h_trans(vq, Vb + (kc + brow) * 72 + nb * 16 + bcof);
#pragma unroll
                for (int blk = 0; blk < 2; blk++) {
                    uint32_t b2[2] = { vq[blk], vq[blk + 2] };
                    mma_f16(accO[nb * 2 + blk], af, b2);
                }
            }
        }
        __syncwarp();
    }

    float inv0 = 1.0f / lr0, inv1 = 1.0f / lr1;
    int r0 = qt * 128 + w * 16 + g;
    int r1 = r0 + 8;
#pragma unroll
    for (int nf = 0; nf < 8; nf++) {
        int colb = nf * 8 + tig * 2;
        if (r0 < Sc)
            *(__half2*)(om2 + ((long long)b * Sc + r0) * Dc + h * 64 + colb) =
                __floats2half2_rn(accO[nf][0] * inv0, accO[nf][1] * inv0);
        if (r1 < Sc)
            *(__half2*)(om2 + ((long long)b * Sc + r1) * Dc + h * 64 + colb) =
                __floats2half2_rn(accO[nf][2] * inv1, accO[nf][3] * inv1);
    }
}

// ---------------- producers / prep ----------------
__global__ void im2col_kernel(const float* __restrict__ x, __half* __restrict__ col) {
    long long idx = (long long)blockIdx.x * blockDim.x + threadIdx.x;
    long long total = (long long)Bc * NP * Dc;
    if (idx >= total) return;
    int k = (int)(idx % Dc);
    int rem = (int)(idx / Dc);
    int p = rem % NP;
    int b = rem / NP;
    int ph = p / GRID24, pw = p % GRID24;
    int ci = k / 256, k2 = k % 256;
    int kh = k2 / 16, kw = k2 % 16;
    col[idx] = __float2half(x[(((long long)b * 3 + ci) * IMGc + ph * 16 + kh) * IMGc + pw * 16 + kw]);
}

__global__ void transpose_wqkv_kernel(const float* __restrict__ w, __half* __restrict__ wt) {
    long long idx = (long long)blockIdx.x * blockDim.x + threadIdx.x;
    long long total = (long long)Lc * 3 * Dc * Dc;
    if (idx >= total) return;
    int d = (int)(idx % Dc);
    int rem = (int)(idx / Dc);
    int n = rem % (3 * Dc);
    int l = rem / (3 * Dc);
    int h = n / 192, e = n % 192;
    wt[idx] = __float2half(w[(((long long)l * Hc + h) * Dc + d) * 192 + e]);
}

__device__ __forceinline__ void btrans_tile(const float* inl, __half* outl,
                                            int R, int Cn, int ct, int rt,
                                            int tx, int ty, float tile[32][33]) {
#pragma unroll
    for (int j = 0; j < 4; j++) {
        int r = rt * 32 + ty + j * 8;
        int c = ct * 32 + tx;
        tile[ty + j * 8][tx] = (r < R && c < Cn) ? inl[(long long)r * Cn + c] : 0.f;
    }
    __syncthreads();
#pragma unroll
    for (int j = 0; j < 4; j++) {
        int c = ct * 32 + ty + j * 8;
        int r = rt * 32 + tx;
        if (c < Cn && r < R)
            outl[(long long)c * R + r] = __float2half(tile[tx][ty + j * 8]);
    }
}

static const int NT_WM = 24 * 24 * Lc;
static const int NT_W1 = 96 * 24 * Lc;
static const int NT_W2 = 24 * 96 * Lc;

__global__ void btrans_multi_kernel(const float* __restrict__ wmsa, __half* __restrict__ wm2,
                                    const float* __restrict__ w1, __half* __restrict__ w12,
                                    const float* __restrict__ w2, __half* __restrict__ w22) {
    __shared__ float tile[32][33];
    int bx = blockIdx.x;
    int tx = threadIdx.x, ty = threadIdx.y;
    if (bx < NT_WM) {
        int l = bx / (24 * 24), rem = bx % (24 * 24);
        int rt = rem / 24, ct = rem % 24;
        btrans_tile(wmsa + (long long)l * Dc * Dc, wm2 + (long long)l * Dc * Dc,
                    Dc, Dc, ct, rt, tx, ty, tile);
    } else if (bx < NT_WM + NT_W1) {
        int b2 = bx - NT_WM;
        int l = b2 / (96 * 24), rem = b2 % (96 * 24);
        int rt = rem / 96, ct = rem % 96;
        btrans_tile(w1 + (long long)l * Dc * Mc, w12 + (long long)l * Dc * Mc,
                    Dc, Mc, ct, rt, tx, ty, tile);
    } else {
        int b2 = bx - NT_WM - NT_W1;
        int l = b2 / (24 * 96), rem = b2 % (24 * 96);
        int rt = rem / 24, ct = rem % 24;
        btrans_tile(w2 + (long long)l * Mc * Dc, w22 + (long long)l * Mc * Dc,
                    Mc, Dc, ct, rt, tx, ty, tile);
    }
}

__global__ void btrans_h_kernel(const float* __restrict__ in, __half* __restrict__ out,
                                int R, int Cn) {
    __shared__ float tile[32][33];
    btrans_tile(in, out, R, Cn, blockIdx.x, blockIdx.y, threadIdx.x, threadIdx.y, tile);
}

__global__ void hcopy_kernel(const float* __restrict__ w, __half* __restrict__ o, long long n) {
    long long i = (long long)blockIdx.x * blockDim.x + threadIdx.x;
    if (i < n) o[i] = __float2half(w[i]);
}

__global__ void embed_kernel(const float* __restrict__ pout, const float* __restrict__ cls,
                             const float* __restrict__ pos, float* __restrict__ t) {
    long long idx = (long long)blockIdx.x * blockDim.x + threadIdx.x;
    long long total = (long long)Bc * Sc * Dc;
    if (idx >= total) return;
    int j = (int)(idx % Dc);
    int rem = (int)(idx / Dc);
    int r = rem % Sc;
    int b = rem / Sc;
    float v;
    if (r == 0) {
        v = cls[j];
    } else {
        int i = (r - 1) * Dc + j;
        int c = i / NP, p = i % NP;
        v = pout[((long long)b * NP + p) * Dc + c];
    }
    t[idx] = v + pos[r * Dc + j];
}

// single LN -> fp16 only
__global__ void layernorm_kernel(const float* __restrict__ x, const float* __restrict__ g,
                                 const float* __restrict__ b, __half* __restrict__ y2, int rows) {
    __shared__ float red[256];
    int row = blockIdx.x;
    if (row >= rows) return;
    int t = threadIdx.x;
    const float* xr = x + (long long)row * Dc;
    float v[3];
    float s = 0.f;
#pragma unroll
    for (int i = 0; i < 3; i++) { v[i] = xr[t + i * 256]; s += v[i]; }
    red[t] = s; __syncthreads();
    for (int o = 128; o > 0; o >>= 1) { if (t < o) red[t] += red[t + o]; __syncthreads(); }
    float mu = red[0] / Dc;
    __syncthreads();
    float s2 = 0.f;
#pragma unroll
    for (int i = 0; i < 3; i++) { float d = v[i] - mu; s2 += d * d; }
    red[t] = s2; __syncthreads();
    for (int o = 128; o > 0; o >>= 1) { if (t < o) red[t] += red[t + o]; __syncthreads(); }
    float rstd = rsqrtf(red[0] / Dc + 1e-5f);
#pragma unroll
    for (int i = 0; i < 3; i++) {
        int j = t + i * 256;
        y2[(long long)row * Dc + j] = __float2half((v[i] - mu) * rstd * g[j] + b[j]);
    }
}

// final LN over cls rows gathered from t (row stride Sc*Dc)
__global__ void layernorm_cls_kernel(const float* __restrict__ tfull,
                                     const float* __restrict__ g, const float* __restrict__ b,
                                     __half* __restrict__ y2, int rows) {
    __shared__ float red[256];
    int row = blockIdx.x;
    if (row >= rows) return;
    int t = threadIdx.x;
    const float* xr = tfull + (long long)row * Sc * Dc;
    float v[3];
    float s = 0.f;
#pragma unroll
    for (int i = 0; i < 3; i++) { v[i] = xr[t + i * 256]; s += v[i]; }
    red[t] = s; __syncthreads();
    for (int o = 128; o > 0; o >>= 1) { if (t < o) red[t] += red[t + o]; __syncthreads(); }
    float mu = red[0] / Dc;
    __syncthreads();
    float s2 = 0.f;
#pragma unroll
    for (int i = 0; i < 3; i++) { float d = v[i] - mu; s2 += d * d; }
    red[t] = s2; __syncthreads();
    for (int o = 128; o > 0; o >>= 1) { if (t < o) red[t] += red[t + o]; __syncthreads(); }
    float rstd = rsqrtf(red[0] / Dc + 1e-5f);
#pragma unroll
    for (int i = 0; i < 3; i++) {
        int j = t + i * 256;
        y2[(long long)row * Dc + j] = __float2half((v[i] - mu) * rstd * g[j] + b[j]);
    }
}

__global__ void layernorm2_kernel(const float* __restrict__ x,
                                  const float* __restrict__ g1, const float* __restrict__ b1,
                                  const float* __restrict__ g2, const float* __restrict__ b2,
                                  __half* __restrict__ y2, int rows) {
    __shared__ float red[256];
    int row = blockIdx.x;
    if (row >= rows) return;
    int t = threadIdx.x;
    const float* xr = x + (long long)row * Dc;
    float v[3];
    float s = 0.f;
#pragma unroll
    for (int i = 0; i < 3; i++) { v[i] = xr[t + i * 256]; s += v[i]; }
    red[t] = s; __syncthreads();
    for (int o = 128; o > 0; o >>= 1) { if (t < o) red[t] += red[t + o]; __syncthreads(); }
    float mu = red[0] / Dc;
    __syncthreads();
    float s2 = 0.f;
#pragma unroll
    for (int i = 0; i < 3; i++) { float d = v[i] - mu; s2 += d * d; }
    red[t] = s2; __syncthreads();
    for (int o = 128; o > 0; o >>= 1) { if (t < o) red[t] += red[t + o]; __syncthreads(); }
    float rstd = rsqrtf(red[0] / Dc + 1e-5f);
    __syncthreads();
    s = 0.f;
#pragma unroll
    for (int i = 0; i < 3; i++) {
        int j = t + i * 256;
        v[i] = (v[i] - mu) * rstd * g1[j] + b1[j];
        s += v[i];
    }
    red[t] = s; __syncthreads();
    for (int o = 128; o > 0; o >>= 1) { if (t < o) red[t] += red[t + o]; __syncthreads(); }
    mu = red[0] / Dc;
    __syncthreads();
    s2 = 0.f;
#pragma unroll
    for (int i = 0; i < 3; i++) { float d = v[i] - mu; s2 += d * d; }
    red[t] = s2; __syncthreads();
    for (int o = 128; o > 0; o >>= 1) { if (t < o) red[t] += red[t + o]; __syncthreads(); }
    rstd = rsqrtf(red[0] / Dc + 1e-5f);
#pragma unroll
    for (int i = 0; i < 3; i++) {
        int j = t + i * 256;
        y2[(long long)row * Dc + j] = __float2half((v[i] - mu) * rstd * g2[j] + b2[j]);
    }
}

__global__ void softmax_kernel(float* __restrict__ x, long long rows, int n) {
    __shared__ float red[256];
    long long row = blockIdx.x;
    if (row >= rows) return;
    int t = threadIdx.x;
    float* xr = x + row * n;
    float lmax = -1e30f;
    for (int j = t; j < n; j += 256) lmax = fmaxf(lmax, xr[j]);
    red[t] = lmax; __syncthreads();
    for (int o = 128; o > 0; o >>= 1) { if (t < o) red[t] = fmaxf(red[t], red[t + o]); __syncthreads(); }
    float mx = red[0];
    __syncthreads();
    float ls = 0.f;
    for (int j = t; j < n; j += 256) { float e = expf(xr[j] - mx); xr[j] = e; ls += e; }
    red[t] = ls; __syncthreads();
    for (int o = 128; o > 0; o >>= 1) { if (t < o) red[t] += red[t + o]; __syncthreads(); }
    float inv = 1.0f / red[0];
    for (int j = t; j < n; j += 256) xr[j] *= inv;
}

// ---------------- host helpers ----------------
static void run_hgemm(const __half* A, const __half* Bm, const float* bias,
                      const float* res, const __half* res2,
                      float* Cf, __half* C2, int M, int N, int K,
                      int ldc, int act) {
    dim3 grid((N + 127) / 128, (M + 127) / 128, 1);
    hgemm_kernel<<<grid, 256, GEMM_SMEM>>>(A, Bm, bias, res, res2, Cf, C2, M, N, K, ldc, act);
}

extern "C" void kernel_launch(void* const* d_in, const int* in_sizes, int n_in,
                              void* d_out, int out_size) {
    const float* x       = (const float*)d_in[0];
    const float* conv_w  = (const float*)d_in[1];
    const float* conv_b  = (const float*)d_in[2];
    const float* cls_tok = (const float*)d_in[3];
    const float* pos_emb = (const float*)d_in[4];
    const float* ln1_g   = (const float*)d_in[5];
    const float* ln1_b   = (const float*)d_in[6];
    const float* wqkv    = (const float*)d_in[7];
    const float* bqkv    = (const float*)d_in[8];
    const float* wmsa    = (const float*)d_in[9];
    const float* bmsa    = (const float*)d_in[10];
    const float* ln2_g   = (const float*)d_in[11];
    const float* ln2_b   = (const float*)d_in[12];
    const float* lnm_g   = (const float*)d_in[13];
    const float* lnm_b   = (const float*)d_in[14];
    const float* w1      = (const float*)d_in[15];
    const float* b1      = (const float*)d_in[16];
    const float* w2      = (const float*)d_in[17];
    const float* b2      = (const float*)d_in[18];
    const float* lnf_g   = (const float*)d_in[19];
    const float* lnf_b   = (const float*)d_in[20];
    const float* whead   = (const float*)d_in[21];
    const float* bhead   = (const float*)d_in[22];
    float* out = (float*)d_out;

    float *t_, *h_;
    __half *h2_, *om2_, *mb2_, *qkv2_, *col2_, *cls2_, *wq2_, *cw2_, *wm2_, *w12_, *w22_, *wh2_;
    cudaGetSymbolAddress((void**)&t_,  g_t);
    cudaGetSymbolAddress((void**)&h_,  g_h);
    cudaGetSymbolAddress((void**)&h2_, g_h2);
    cudaGetSymbolAddress((void**)&om2_, g_om2);
    cudaGetSymbolAddress((void**)&mb2_, g_mb2);
    cudaGetSymbolAddress((void**)&qkv2_, g_qkv2);
    cudaGetSymbolAddress((void**)&col2_, g_col2);
    cudaGetSymbolAddress((void**)&cls2_, g_cls2);
    cudaGetSymbolAddress((void**)&wq2_, g_wq2);
    cudaGetSymbolAddress((void**)&cw2_, g_cw2);
    cudaGetSymbolAddress((void**)&wm2_, g_wm2);
    cudaGetSymbolAddress((void**)&w12_, g_w12);
    cudaGetSymbolAddress((void**)&w22_, g_w22);
    cudaGetSymbolAddress((void**)&wh2_, g_wh2);

    cudaFuncSetAttribute(flash_kernel, cudaFuncAttributeMaxDynamicSharedMemorySize, FLASH_SMEM);
    cudaFuncSetAttribute(hgemm_kernel, cudaFuncAttributeMaxDynamicSharedMemorySize, GEMM_SMEM);

    // --- prep ---
    hcopy_kernel<<<(Dc * Dc + 255) / 256, 256>>>(conv_w, cw2_, (long long)Dc * Dc);
    {
        long long tot = (long long)Lc * 3 * Dc * Dc;
        transpose_wqkv_kernel<<<(int)((tot + 255) / 256), 256>>>(wqkv, wq2_);
    }
    btrans_multi_kernel<<<NT_WM + NT_W1 + NT_W2, dim3(32, 8)>>>(wmsa, wm2_, w1, w12_,
                                                                w2, w22_);
    btrans_h_kernel<<<dim3((NCc + 31) / 32, Dc / 32), dim3(32, 8)>>>(whead, wh2_, Dc, NCc);
    {
        long long tot = (long long)Bc * NP * Dc;
        im2col_kernel<<<(int)((tot + 255) / 256), 256>>>(x, col2_);
    }
    run_hgemm(col2_, cw2_, conv_b, nullptr, nullptr, h_, nullptr, Bc * NP, Dc, Dc, Dc, 0);
    {
        long long tot = (long long)Bc * Sc * Dc;
        embed_kernel<<<(int)((tot + 255) / 256), 256>>>(h_, cls_tok, pos_emb, t_);
    }

    // --- encoder layers ---
    for (int l = 0; l < Lc; l++) {
        layernorm_kernel<<<BS, 256>>>(t_, ln1_g + l * Dc, ln1_b + l * Dc, h2_, BS);
        run_hgemm(h2_, wq2_ + (long long)l * 3 * Dc * Dc, bqkv + l * 3 * Dc, nullptr, nullptr,
                  nullptr, qkv2_, BS, 3 * Dc, Dc, 3 * Dc, 0);
        flash_kernel<<<dim3((Sc + 127) / 128, Hc, Bc), 256, FLASH_SMEM>>>(qkv2_, om2_);
        run_hgemm(om2_, wm2_ + (long long)l * Dc * Dc, bmsa + l * Dc, nullptr, h2_,
                  t_, nullptr, BS, Dc, Dc, Dc, 0);
        layernorm2_kernel<<<BS, 256>>>(t_, ln2_g + l * Dc, ln2_b + l * Dc,
                                       lnm_g + l * Dc, lnm_b + l * Dc, h2_, BS);
        run_hgemm(h2_, w12_ + (long long)l * Mc * Dc, b1 + l * Mc, nullptr, nullptr,
                  nullptr, mb2_, BS, Mc, Dc, Mc, 1);
        run_hgemm(mb2_, w22_ + (long long)l * Dc * Mc, b2 + l * Dc, t_, nullptr,
                  t_, nullptr, BS, Dc, Mc, Dc, 0);
    }

    // --- head ---
    layernorm_cls_kernel<<<Bc, 256>>>(t_, lnf_g, lnf_b, cls2_, Bc);
    run_hgemm(cls2_, wh2_, bhead, nullptr, nullptr, out, nullptr, Bc, NCc, Dc, NCc, 0);
    softmax_kernel<<<Bc, 256>>>(out, Bc, NCc);
}

// round 17
// speedup vs baseline: 1.1693x; 1.0929x over previous
#include <cuda_runtime.h>
#include <cuda_fp16.h>
#include <math.h>
#include <stdint.h>

// ---------------- dims ----------------
static const int Lc = 12, Hc = 12, Dc = 768, HDc = 64, Mc = 3072;
static const int IMGc = 384, Bc = 32, NCc = 1000;
static const int NP = 576;
static const int Sc = 577;
static const int BS = Bc * Sc;        // 18464
static const int GRID24 = 24;
static const int GS = 3;              // gemm pipeline stages (BK=64)

// ---------------- scratch ----------------
__device__ float g_t[BS * Dc];                 // residual (fp32)
__device__ float g_h[BS * Dc];                 // patchify gemm out (fp32)
// fp16 operands
__device__ __half g_h2[BS * Dc];
__device__ __half g_om2[BS * Dc];
__device__ __half g_mb2[(long long)BS * Mc];
__device__ __half g_qkv2[(long long)BS * 3 * Dc];
__device__ __half g_col2[Bc * NP * Dc];
__device__ __half g_cls2[Bc * Dc];
__device__ __half g_wq2[(long long)Lc * 3 * Dc * Dc];  // [l][n=2304][k=768]
__device__ __half g_cw2[Dc * Dc];                      // [n][k]
__device__ __half g_wm2[(long long)Lc * Dc * Dc];
__device__ __half g_w12[(long long)Lc * Mc * Dc];
__device__ __half g_w22[(long long)Lc * Dc * Mc];
__device__ __half g_wh2[NCc * Dc];

// ---------------- helpers ----------------
__device__ __forceinline__ void mma_f16(float c[4], const uint32_t a[4], const uint32_t b[2]) {
    asm volatile(
        "mma.sync.aligned.m16n8k16.row.col.f32.f16.f16.f32 "
        "{%0,%1,%2,%3}, {%4,%5,%6,%7}, {%8,%9}, {%0,%1,%2,%3};\n"
        : "+f"(c[0]), "+f"(c[1]), "+f"(c[2]), "+f"(c[3])
        : "r"(a[0]), "r"(a[1]), "r"(a[2]), "r"(a[3]), "r"(b[0]), "r"(b[1]));
}

__device__ __forceinline__ void cp_async16(void* smem_dst, const void* gsrc, int sz) {
    unsigned sm = (unsigned)__cvta_generic_to_shared(smem_dst);
    asm volatile("cp.async.cg.shared.global [%0], [%1], 16, %2;\n" :: "r"(sm), "l"(gsrc), "r"(sz));
}

__device__ __forceinline__ void ldsm4h(uint32_t r[4], const __half* p) {
    unsigned a = (unsigned)__cvta_generic_to_shared(p);
    asm volatile("ldmatrix.sync.aligned.m8n8.x4.shared.b16 {%0,%1,%2,%3}, [%4];\n"
                 : "=r"(r[0]), "=r"(r[1]), "=r"(r[2]), "=r"(r[3]) : "r"(a));
}
__device__ __forceinline__ void ldsm4h_trans(uint32_t r[4], const __half* p) {
    unsigned a = (unsigned)__cvta_generic_to_shared(p);
    asm volatile("ldmatrix.sync.aligned.m8n8.x4.trans.shared.b16 {%0,%1,%2,%3}, [%4];\n"
                 : "=r"(r[0]), "=r"(r[1]), "=r"(r[2]), "=r"(r[3]) : "r"(a));
}

// ---------------- fp16 tensor GEMM: BK=64, GS=3 ----------------
static const int HROW = 72;                      // halves per row (64 + 8 pad)
static const int HSTG = 128 * HROW;              // halves per operand per stage
static const int GEMM_SMEM = GS * 2 * HSTG * 2;  // 110592 bytes

__global__ void __launch_bounds__(256, 2)
hgemm_kernel(const __half* __restrict__ A, const __half* __restrict__ Bm,
             const float* __restrict__ bias, const float* __restrict__ res,
             const __half* __restrict__ res2,
             float* __restrict__ Cf, __half* __restrict__ C2,
             int M, int N, int K, int ldc, int act) {
    extern __shared__ __half smh[];

    int t = threadIdx.x;
    int lane = t & 31, wid = t >> 5;
    int wm = wid >> 2, wn = wid & 3;
    int g = lane >> 2, tig = lane & 3;
    int m0 = blockIdx.y * 128, n0 = blockIdx.x * 128;

    float acc[4][4][4] = {};
    int nk = K / 64;

    auto loadTile = [&](int k0, int s) {
        __half* dstA = smh + s * 2 * HSTG;
        __half* dstB = dstA + HSTG;
#pragma unroll
        for (int i = 0; i < 4; i++) {
            int c = t + i * 256;
            int r = c >> 3, sg = (c & 7) * 8;
            cp_async16(dstA + r * HROW + sg, A + (long long)(m0 + r) * K + k0 + sg,
                       (m0 + r < M) ? 16 : 0);
        }
#pragma unroll
        for (int i = 0; i < 4; i++) {
            int c = t + i * 256;
            int r = c >> 3, sg = (c & 7) * 8;
            cp_async16(dstB + r * HROW + sg, Bm + (long long)(n0 + r) * K + k0 + sg,
                       (n0 + r < N) ? 16 : 0);
        }
    };

#pragma unroll
    for (int s = 0; s < GS - 1; s++) {
        loadTile(s * 64, s);
        asm volatile("cp.async.commit_group;\n");
    }

    int a_row = wm * 64 + (lane & 15);
    int a_cofs = (lane >> 4) << 3;
    int b_row = wn * 32 + ((lane >> 4) << 3) + (lane & 7);
    int b_cofs = ((lane >> 3) & 1) << 3;

    for (int it = 0; it < nk; it++) {
        asm volatile("cp.async.wait_group %0;\n" :: "n"(GS - 2));
        __syncthreads();
        if (it + GS - 1 < nk) loadTile((it + GS - 1) * 64, (it + GS - 1) % GS);
        asm volatile("cp.async.commit_group;\n");

        const __half* Ab = smh + (it % GS) * 2 * HSTG;
        const __half* Bb = Ab + HSTG;
#pragma unroll
        for (int ks = 0; ks < 4; ks++) {
            int kc = ks * 16;
            uint32_t af[4][4], bq[2][4];
#pragma unroll
            for (int mt = 0; mt < 4; mt++)
                ldsm4h(af[mt], Ab + (a_row + mt * 16) * HROW + kc + a_cofs);
#pragma unroll
            for (int nb = 0; nb < 2; nb++)
                ldsm4h(bq[nb], Bb + (b_row + nb * 16) * HROW + kc + b_cofs);
#pragma unroll
            for (int mt = 0; mt < 4; mt++)
#pragma unroll
                for (int nt = 0; nt < 4; nt++) {
                    uint32_t b2[2] = { bq[nt >> 1][(nt & 1) * 2], bq[nt >> 1][(nt & 1) * 2 + 1] };
                    mma_f16(acc[mt][nt], af[mt], b2);
                }
        }
    }

    // epilogue: vectorized (col, col+1) pair loads/stores
#pragma unroll
    for (int mt = 0; mt < 4; mt++) {
#pragma unroll
        for (int nt = 0; nt < 4; nt++) {
            int row = m0 + wm * 64 + mt * 16 + g;
            int col = n0 + wn * 32 + nt * 8 + tig * 2;
            if (col >= N) continue;
            int pair = (col + 1 < N);
#pragma unroll
            for (int hp = 0; hp < 2; hp++) {
                int m = row + hp * 8;
                if (m >= M) continue;
                float v0 = acc[mt][nt][hp * 2];
                float v1 = acc[mt][nt][hp * 2 + 1];
                if (bias) { v0 += bias[col]; if (pair) v1 += bias[col + 1]; }
                if (res) {
                    if (pair) {
                        float2 r2 = *(const float2*)(res + (long long)m * ldc + col);
                        v0 += r2.x; v1 += r2.y;
                    } else {
                        v0 += res[(long long)m * ldc + col];
                    }
                }
                if (res2) {
                    if (pair) {
                        __half2 r2 = *(const __half2*)(res2 + (long long)m * ldc + col);
                        v0 += __low2float(r2);
                        v1 += __high2float(r2);
                    } else {
                        v0 += __half2float(res2[(long long)m * ldc + col]);
                    }
                }
                if (act == 1) {
                    v0 = 0.5f * v0 * (1.0f + erff(v0 * 0.7071067811865476f));
                    v1 = 0.5f * v1 * (1.0f + erff(v1 * 0.7071067811865476f));
                }
                if (Cf) {
                    if (pair)
                        *(float2*)(Cf + (long long)m * ldc + col) = make_float2(v0, v1);
                    else
                        Cf[(long long)m * ldc + col] = v0;
                }
                if (C2) {
                    if (pair)
                        *(__half2*)(C2 + (long long)m * ldc + col) = __floats2half2_rn(v0, v1);
                    else
                        C2[(long long)m * ldc + col] = __float2half(v0);
                }
            }
        }
    }
}

// ---------------- fp16 flash attention: 3-stage K/V pipeline, Q frags hoisted ----------------
static const int FLASH_SMEM = (9216 + 9216 + 13824 + 13824) * 2;   // 92160 B

__global__ void __launch_bounds__(256, 2)
flash_kernel(const __half* __restrict__ qkv, __half* __restrict__ om2) {
    extern __shared__ __half smh[];
    __half* Qs = smh;               // [128][72]
    __half* Ps = smh + 9216;        // [8][16][72]
    __half* Ks = smh + 18432;       // [3][64][72]
    __half* Vs = smh + 32256;       // [3][64][72]

    int qt = blockIdx.x, h = blockIdx.y, b = blockIdx.z;
    int t = threadIdx.x, lane = t & 31, w = t >> 5, g = lane >> 2, tig = lane & 3;
    const __half* qb = qkv + (long long)b * Sc * 2304 + h * 192;

#pragma unroll
    for (int i = 0; i < 4; i++) {
        int idx = t + i * 256;
        int row = idx >> 3, sg = idx & 7;
        int gr = qt * 128 + row;
        cp_async16(Qs + row * 72 + sg * 8, qb + (long long)gr * 2304 + sg * 8, gr < Sc ? 16 : 0);
    }
    auto issueKV = [&](int kt_, int buf) {
#pragma unroll
        for (int i = 0; i < 2; i++) {
            int idx = t + i * 256;
            int row = idx >> 3, sg = idx & 7;
            int gk = kt_ * 64 + row;
            cp_async16(Ks + (buf * 64 + row) * 72 + sg * 8,
                       qb + (long long)gk * 2304 + 64 + sg * 8, gk < Sc ? 16 : 0);
        }
#pragma unroll
        for (int i = 0; i < 2; i++) {
            int idx = t + i * 256;
            int row = idx >> 3, sg = idx & 7;
            int gk = kt_ * 64 + row;
            cp_async16(Vs + (buf * 64 + row) * 72 + sg * 8,
                       qb + (long long)gk * 2304 + 128 + sg * 8, gk < Sc ? 16 : 0);
        }
    };
    const int nt = (Sc + 63) / 64;   // 10
    issueKV(0, 0);
    asm volatile("cp.async.commit_group;\n");
    issueKV(1, 1);
    asm volatile("cp.async.commit_group;\n");

    float accO[8][4] = {};
    float mr0 = -1e30f, mr1 = -1e30f, lr0 = 0.f, lr1 = 0.f;
    __half* Pw = Ps + w * 16 * 72;
    const __half* Qw = Qs + w * 16 * 72;

    int arow = lane & 15;
    int acof = (lane >> 4) << 3;
    int brow = ((lane >> 4) << 3) + (lane & 7);
    int bcof = ((lane >> 3) & 1) << 3;

    asm volatile("cp.async.wait_group 1;\n");
    __syncthreads();
    uint32_t afq[4][4];
#pragma unroll
    for (int ks = 0; ks < 4; ks++)
        ldsm4h(afq[ks], Qw + arow * 72 + ks * 16 + acof);

    for (int kt_ = 0; kt_ < nt; kt_++) {
        int buf = kt_ % 3;
        asm volatile("cp.async.wait_group 1;\n");
        __syncthreads();
        if (kt_ + 2 < nt) issueKV(kt_ + 2, (kt_ + 2) % 3);
        asm volatile("cp.async.commit_group;\n");

        float s[8][4] = {};
        const __half* Kb = Ks + buf * 64 * 72;
#pragma unroll
        for (int ks = 0; ks < 4; ks++) {
            int kc = ks * 16;
#pragma unroll
            for (int nb = 0; nb < 4; nb++) {
                uint32_t bq[4];
                ldsm4h(bq, Kb + (nb * 16 + brow) * 72 + kc + bcof);
#pragma unroll
                for (int blk = 0; blk < 2; blk++) {
                    uint32_t b2[2] = { bq[blk * 2], bq[blk * 2 + 1] };
                    mma_f16(s[nb * 2 + blk], afq[ks], b2);
                }
            }
        }
        float rm0 = -1e30f, rm1 = -1e30f;
#pragma unroll
        for (int nf = 0; nf < 8; nf++) {
#pragma unroll
            for (int cc = 0; cc < 4; cc++) {
                int col = kt_ * 64 + nf * 8 + tig * 2 + (cc & 1);
                float v = s[nf][cc] * 0.125f;
                v = (col < Sc) ? v : -1e30f;
                s[nf][cc] = v;
                if (cc < 2) rm0 = fmaxf(rm0, v); else rm1 = fmaxf(rm1, v);
            }
        }
        rm0 = fmaxf(rm0, __shfl_xor_sync(0xffffffffu, rm0, 1));
        rm0 = fmaxf(rm0, __shfl_xor_sync(0xffffffffu, rm0, 2));
        rm1 = fmaxf(rm1, __shfl_xor_sync(0xffffffffu, rm1, 1));
        rm1 = fmaxf(rm1, __shfl_xor_sync(0xffffffffu, rm1, 2));
        float nm0 = fmaxf(mr0, rm0), nm1 = fmaxf(mr1, rm1);
        float cor0 = __expf(mr0 - nm0), cor1 = __expf(mr1 - nm1);
        float rs0 = 0.f, rs1 = 0.f;
#pragma unroll
        for (int nf = 0; nf < 8; nf++) {
            int colb = nf * 8 + tig * 2;
            float p0 = __expf(s[nf][0] - nm0);
            float p1 = __expf(s[nf][1] - nm0);
            float p2 = __expf(s[nf][2] - nm1);
            float p3 = __expf(s[nf][3] - nm1);
            rs0 += p0 + p1; rs1 += p2 + p3;
            *(__half2*)(Pw + g * 72 + colb)       = __floats2half2_rn(p0, p1);
            *(__half2*)(Pw + (g + 8) * 72 + colb) = __floats2half2_rn(p2, p3);
        }
        rs0 += __shfl_xor_sync(0xffffffffu, rs0, 1);
        rs0 += __shfl_xor_sync(0xffffffffu, rs0, 2);
        rs1 += __shfl_xor_sync(0xffffffffu, rs1, 1);
        rs1 += __shfl_xor_sync(0xffffffffu, rs1, 2);
        lr0 = lr0 * cor0 + rs0;
        lr1 = lr1 * cor1 + rs1;
        mr0 = nm0; mr1 = nm1;
#pragma unroll
        for (int nf = 0; nf < 8; nf++) {
            accO[nf][0] *= cor0; accO[nf][1] *= cor0;
            accO[nf][2] *= cor1; accO[nf][3] *= cor1;
        }
        __syncwarp();
        const __half* Vb = Vs + buf * 64 * 72;
#pragma unroll
        for (int ks = 0; ks < 4; ks++) {
            int kc = ks * 16;
            uint32_t af[4];
            ldsm4h(af, Pw + arow * 72 + kc + acof);
#pragma unroll
            for (int nb = 0; nb < 4; nb++) {
                uint32_t vq[4];
                ldsm4h_trans(vq, Vb + (kc + brow) * 72 + nb * 16 + bcof);
#pragma unroll
                for (int blk = 0; blk < 2; blk++) {
                    uint32_t b2[2] = { vq[blk], vq[blk + 2] };
                    mma_f16(accO[nb * 2 + blk], af, b2);
                }
            }
        }
        __syncwarp();
    }

    float inv0 = 1.0f / lr0, inv1 = 1.0f / lr1;
    int r0 = qt * 128 + w * 16 + g;
    int r1 = r0 + 8;
#pragma unroll
    for (int nf = 0; nf < 8; nf++) {
        int colb = nf * 8 + tig * 2;
        if (r0 < Sc)
            *(__half2*)(om2 + ((long long)b * Sc + r0) * Dc + h * 64 + colb) =
                __floats2half2_rn(accO[nf][0] * inv0, accO[nf][1] * inv0);
        if (r1 < Sc)
            *(__half2*)(om2 + ((long long)b * Sc + r1) * Dc + h * 64 + colb) =
                __floats2half2_rn(accO[nf][2] * inv1, accO[nf][3] * inv1);
    }
}

// ---------------- producers / prep ----------------
__global__ void im2col_kernel(const float* __restrict__ x, __half* __restrict__ col) {
    long long idx = (long long)blockIdx.x * blockDim.x + threadIdx.x;
    long long total = (long long)Bc * NP * Dc;
    if (idx >= total) return;
    int k = (int)(idx % Dc);
    int rem = (int)(idx / Dc);
    int p = rem % NP;
    int b = rem / NP;
    int ph = p / GRID24, pw = p % GRID24;
    int ci = k / 256, k2 = k % 256;
    int kh = k2 / 16, kw = k2 % 16;
    col[idx] = __float2half(x[(((long long)b * 3 + ci) * IMGc + ph * 16 + kh) * IMGc + pw * 16 + kw]);
}

__global__ void transpose_wqkv_kernel(const float* __restrict__ w, __half* __restrict__ wt) {
    long long idx = (long long)blockIdx.x * blockDim.x + threadIdx.x;
    long long total = (long long)Lc * 3 * Dc * Dc;
    if (idx >= total) return;
    int d = (int)(idx % Dc);
    int rem = (int)(idx / Dc);
    int n = rem % (3 * Dc);
    int l = rem / (3 * Dc);
    int h = n / 192, e = n % 192;
    wt[idx] = __float2half(w[(((long long)l * Hc + h) * Dc + d) * 192 + e]);
}

__device__ __forceinline__ void btrans_tile(const float* inl, __half* outl,
                                            int R, int Cn, int ct, int rt,
                                            int tx, int ty, float tile[32][33]) {
#pragma unroll
    for (int j = 0; j < 4; j++) {
        int r = rt * 32 + ty + j * 8;
        int c = ct * 32 + tx;
        tile[ty + j * 8][tx] = (r < R && c < Cn) ? inl[(long long)r * Cn + c] : 0.f;
    }
    __syncthreads();
#pragma unroll
    for (int j = 0; j < 4; j++) {
        int c = ct * 32 + ty + j * 8;
        int r = rt * 32 + tx;
        if (c < Cn && r < R)
            outl[(long long)c * R + r] = __float2half(tile[tx][ty + j * 8]);
    }
}

static const int NT_WM = 24 * 24 * Lc;
static const int NT_W1 = 96 * 24 * Lc;
static const int NT_W2 = 24 * 96 * Lc;

__global__ void btrans_multi_kernel(const float* __restrict__ wmsa, __half* __restrict__ wm2,
                                    const float* __restrict__ w1, __half* __restrict__ w12,
                                    const float* __restrict__ w2, __half* __restrict__ w22) {
    __shared__ float tile[32][33];
    int bx = blockIdx.x;
    int tx = threadIdx.x, ty = threadIdx.y;
    if (bx < NT_WM) {
        int l = bx / (24 * 24), rem = bx % (24 * 24);
        int rt = rem / 24, ct = rem % 24;
        btrans_tile(wmsa + (long long)l * Dc * Dc, wm2 + (long long)l * Dc * Dc,
                    Dc, Dc, ct, rt, tx, ty, tile);
    } else if (bx < NT_WM + NT_W1) {
        int b2 = bx - NT_WM;
        int l = b2 / (96 * 24), rem = b2 % (96 * 24);
        int rt = rem / 96, ct = rem % 96;
        btrans_tile(w1 + (long long)l * Dc * Mc, w12 + (long long)l * Dc * Mc,
                    Dc, Mc, ct, rt, tx, ty, tile);
    } else {
        int b2 = bx - NT_WM - NT_W1;
        int l = b2 / (24 * 96), rem = b2 % (24 * 96);
        int rt = rem / 24, ct = rem % 24;
        btrans_tile(w2 + (long long)l * Mc * Dc, w22 + (long long)l * Mc * Dc,
                    Mc, Dc, ct, rt, tx, ty, tile);
    }
}

__global__ void btrans_h_kernel(const float* __restrict__ in, __half* __restrict__ out,
                                int R, int Cn) {
    __shared__ float tile[32][33];
    btrans_tile(in, out, R, Cn, blockIdx.x, blockIdx.y, threadIdx.x, threadIdx.y, tile);
}

__global__ void hcopy_kernel(const float* __restrict__ w, __half* __restrict__ o, long long n) {
    long long i = (long long)blockIdx.x * blockDim.x + threadIdx.x;
    if (i < n) o[i] = __float2half(w[i]);
}

__global__ void embed_kernel(const float* __restrict__ pout, const float* __restrict__ cls,
                             const float* __restrict__ pos, float* __restrict__ t) {
    long long idx = (long long)blockIdx.x * blockDim.x + threadIdx.x;
    long long total = (long long)Bc * Sc * Dc;
    if (idx >= total) return;
    int j = (int)(idx % Dc);
    int rem = (int)(idx / Dc);
    int r = rem % Sc;
    int b = rem / Sc;
    float v;
    if (r == 0) {
        v = cls[j];
    } else {
        int i = (r - 1) * Dc + j;
        int c = i / NP, p = i % NP;
        v = pout[((long long)b * NP + p) * Dc + c];
    }
    t[idx] = v + pos[r * Dc + j];
}

// single LN -> fp16 only
__global__ void layernorm_kernel(const float* __restrict__ x, const float* __restrict__ g,
                                 const float* __restrict__ b, __half* __restrict__ y2, int rows) {
    __shared__ float red[256];
    int row = blockIdx.x;
    if (row >= rows) return;
    int t = threadIdx.x;
    const float* xr = x + (long long)row * Dc;
    float v[3];
    float s = 0.f;
#pragma unroll
    for (int i = 0; i < 3; i++) { v[i] = xr[t + i * 256]; s += v[i]; }
    red[t] = s; __syncthreads();
    for (int o = 128; o > 0; o >>= 1) { if (t < o) red[t] += red[t + o]; __syncthreads(); }
    float mu = red[0] / Dc;
    __syncthreads();
    float s2 = 0.f;
#pragma unroll
    for (int i = 0; i < 3; i++) { float d = v[i] - mu; s2 += d * d; }
    red[t] = s2; __syncthreads();
    for (int o = 128; o > 0; o >>= 1) { if (t < o) red[t] += red[t + o]; __syncthreads(); }
    float rstd = rsqrtf(red[0] / Dc + 1e-5f);
#pragma unroll
    for (int i = 0; i < 3; i++) {
        int j = t + i * 256;
        y2[(long long)row * Dc + j] = __float2half((v[i] - mu) * rstd * g[j] + b[j]);
    }
}

// final LN over cls rows gathered from t (row stride Sc*Dc)
__global__ void layernorm_cls_kernel(const float* __restrict__ tfull,
                                     const float* __restrict__ g, const float* __restrict__ b,
                                     __half* __restrict__ y2, int rows) {
    __shared__ float red[256];
    int row = blockIdx.x;
    if (row >= rows) return;
    int t = threadIdx.x;
    const float* xr = tfull + (long long)row * Sc * Dc;
    float v[3];
    float s = 0.f;
#pragma unroll
    for (int i = 0; i < 3; i++) { v[i] = xr[t + i * 256]; s += v[i]; }
    red[t] = s; __syncthreads();
    for (int o = 128; o > 0; o >>= 1) { if (t < o) red[t] += red[t + o]; __syncthreads(); }
    float mu = red[0] / Dc;
    __syncthreads();
    float s2 = 0.f;
#pragma unroll
    for (int i = 0; i < 3; i++) { float d = v[i] - mu; s2 += d * d; }
    red[t] = s2; __syncthreads();
    for (int o = 128; o > 0; o >>= 1) { if (t < o) red[t] += red[t + o]; __syncthreads(); }
    float rstd = rsqrtf(red[0] / Dc + 1e-5f);
#pragma unroll
    for (int i = 0; i < 3; i++) {
        int j = t + i * 256;
        y2[(long long)row * Dc + j] = __float2half((v[i] - mu) * rstd * g[j] + b[j]);
    }
}

__global__ void layernorm2_kernel(const float* __restrict__ x,
                                  const float* __restrict__ g1, const float* __restrict__ b1,
                                  const float* __restrict__ g2, const float* __restrict__ b2,
                                  __half* __restrict__ y2, int rows) {
    __shared__ float red[256];
    int row = blockIdx.x;
    if (row >= rows) return;
    int t = threadIdx.x;
    const float* xr = x + (long long)row * Dc;
    float v[3];
    float s = 0.f;
#pragma unroll
    for (int i = 0; i < 3; i++) { v[i] = xr[t + i * 256]; s += v[i]; }
    red[t] = s; __syncthreads();
    for (int o = 128; o > 0; o >>= 1) { if (t < o) red[t] += red[t + o]; __syncthreads(); }
    float mu = red[0] / Dc;
    __syncthreads();
    float s2 = 0.f;
#pragma unroll
    for (int i = 0; i < 3; i++) { float d = v[i] - mu; s2 += d * d; }
    red[t] = s2; __syncthreads();
    for (int o = 128; o > 0; o >>= 1) { if (t < o) red[t] += red[t + o]; __syncthreads(); }
    float rstd = rsqrtf(red[0] / Dc + 1e-5f);
    __syncthreads();
    s = 0.f;
#pragma unroll
    for (int i = 0; i < 3; i++) {
        int j = t + i * 256;
        v[i] = (v[i] - mu) * rstd * g1[j] + b1[j];
        s += v[i];
    }
    red[t] = s; __syncthreads();
    for (int o = 128; o > 0; o >>= 1) { if (t < o) red[t] += red[t + o]; __syncthreads(); }
    mu = red[0] / Dc;
    __syncthreads();
    s2 = 0.f;
#pragma unroll
    for (int i = 0; i < 3; i++) { float d = v[i] - mu; s2 += d * d; }
    red[t] = s2; __syncthreads();
    for (int o = 128; o > 0; o >>= 1) { if (t < o) red[t] += red[t + o]; __syncthreads(); }
    rstd = rsqrtf(red[0] / Dc + 1e-5f);
#pragma unroll
    for (int i = 0; i < 3; i++) {
        int j = t + i * 256;
        y2[(long long)row * Dc + j] = __float2half((v[i] - mu) * rstd * g2[j] + b2[j]);
    }
}

__global__ void softmax_kernel(float* __restrict__ x, long long rows, int n) {
    __shared__ float red[256];
    long long row = blockIdx.x;
    if (row >= rows) return;
    int t = threadIdx.x;
    float* xr = x + row * n;
    float lmax = -1e30f;
    for (int j = t; j < n; j += 256) lmax = fmaxf(lmax, xr[j]);
    red[t] = lmax; __syncthreads();
    for (int o = 128; o > 0; o >>= 1) { if (t < o) red[t] = fmaxf(red[t], red[t + o]); __syncthreads(); }
    float mx = red[0];
    __syncthreads();
    float ls = 0.f;
    for (int j = t; j < n; j += 256) { float e = expf(xr[j] - mx); xr[j] = e; ls += e; }
    red[t] = ls; __syncthreads();
    for (int o = 128; o > 0; o >>= 1) { if (t < o) red[t] += red[t + o]; __syncthreads(); }
    float inv = 1.0f / red[0];
    for (int j = t; j < n; j += 256) xr[j] *= inv;
}

// ---------------- host helpers ----------------
static void run_hgemm(const __half* A, const __half* Bm, const float* bias,
                      const float* res, const __half* res2,
                      float* Cf, __half* C2, int M, int N, int K,
                      int ldc, int act) {
    dim3 grid((N + 127) / 128, (M + 127) / 128, 1);
    hgemm_kernel<<<grid, 256, GEMM_SMEM>>>(A, Bm, bias, res, res2, Cf, C2, M, N, K, ldc, act);
}

extern "C" void kernel_launch(void* const* d_in, const int* in_sizes, int n_in,
                              void* d_out, int out_size) {
    const float* x       = (const float*)d_in[0];
    const float* conv_w  = (const float*)d_in[1];
    const float* conv_b  = (const float*)d_in[2];
    const float* cls_tok = (const float*)d_in[3];
    const float* pos_emb = (const float*)d_in[4];
    const float* ln1_g   = (const float*)d_in[5];
    const float* ln1_b   = (const float*)d_in[6];
    const float* wqkv    = (const float*)d_in[7];
    const float* bqkv    = (const float*)d_in[8];
    const float* wmsa    = (const float*)d_in[9];
    const float* bmsa    = (const float*)d_in[10];
    const float* ln2_g   = (const float*)d_in[11];
    const float* ln2_b   = (const float*)d_in[12];
    const float* lnm_g   = (const float*)d_in[13];
    const float* lnm_b   = (const float*)d_in[14];
    const float* w1      = (const float*)d_in[15];
    const float* b1      = (const float*)d_in[16];
    const float* w2      = (const float*)d_in[17];
    const float* b2      = (const float*)d_in[18];
    const float* lnf_g   = (const float*)d_in[19];
    const float* lnf_b   = (const float*)d_in[20];
    const float* whead   = (const float*)d_in[21];
    const float* bhead   = (const float*)d_in[22];
    float* out = (float*)d_out;

    float *t_, *h_;
    __half *h2_, *om2_, *mb2_, *qkv2_, *col2_, *cls2_, *wq2_, *cw2_, *wm2_, *w12_, *w22_, *wh2_;
    cudaGetSymbolAddress((void**)&t_,  g_t);
    cudaGetSymbolAddress((void**)&h_,  g_h);
    cudaGetSymbolAddress((void**)&h2_, g_h2);
    cudaGetSymbolAddress((void**)&om2_, g_om2);
    cudaGetSymbolAddress((void**)&mb2_, g_mb2);
    cudaGetSymbolAddress((void**)&qkv2_, g_qkv2);
    cudaGetSymbolAddress((void**)&col2_, g_col2);
    cudaGetSymbolAddress((void**)&cls2_, g_cls2);
    cudaGetSymbolAddress((void**)&wq2_, g_wq2);
    cudaGetSymbolAddress((void**)&cw2_, g_cw2);
    cudaGetSymbolAddress((void**)&wm2_, g_wm2);
    cudaGetSymbolAddress((void**)&w12_, g_w12);
    cudaGetSymbolAddress((void**)&w22_, g_w22);
    cudaGetSymbolAddress((void**)&wh2_, g_wh2);

    cudaFuncSetAttribute(flash_kernel, cudaFuncAttributeMaxDynamicSharedMemorySize, FLASH_SMEM);
    cudaFuncSetAttribute(hgemm_kernel, cudaFuncAttributeMaxDynamicSharedMemorySize, GEMM_SMEM);

    // --- prep ---
    hcopy_kernel<<<(Dc * Dc + 255) / 256, 256>>>(conv_w, cw2_, (long long)Dc * Dc);
    {
        long long tot = (long long)Lc * 3 * Dc * Dc;
        transpose_wqkv_kernel<<<(int)((tot + 255) / 256), 256>>>(wqkv, wq2_);
    }
    btrans_multi_kernel<<<NT_WM + NT_W1 + NT_W2, dim3(32, 8)>>>(wmsa, wm2_, w1, w12_,
                                                                w2, w22_);
    btrans_h_kernel<<<dim3((NCc + 31) / 32, Dc / 32), dim3(32, 8)>>>(whead, wh2_, Dc, NCc);
    {
        long long tot = (long long)Bc * NP * Dc;
        im2col_kernel<<<(int)((tot + 255) / 256), 256>>>(x, col2_);
    }
    run_hgemm(col2_, cw2_, conv_b, nullptr, nullptr, h_, nullptr, Bc * NP, Dc, Dc, Dc, 0);
    {
        long long tot = (long long)Bc * Sc * Dc;
        embed_kernel<<<(int)((tot + 255) / 256), 256>>>(h_, cls_tok, pos_emb, t_);
    }

    // --- encoder layers ---
    for (int l = 0; l < Lc; l++) {
        layernorm_kernel<<<BS, 256>>>(t_, ln1_g + l * Dc, ln1_b + l * Dc, h2_, BS);
        run_hgemm(h2_, wq2_ + (long long)l * 3 * Dc * Dc, bqkv + l * 3 * Dc, nullptr, nullptr,
                  nullptr, qkv2_, BS, 3 * Dc, Dc, 3 * Dc, 0);
        flash_kernel<<<dim3((Sc + 127) / 128, Hc, Bc), 256, FLASH_SMEM>>>(qkv2_, om2_);
        run_hgemm(om2_, wm2_ + (long long)l * Dc * Dc, bmsa + l * Dc, nullptr, h2_,
                  t_, nullptr, BS, Dc, Dc, Dc, 0);
        layernorm2_kernel<<<BS, 256>>>(t_, ln2_g + l * Dc, ln2_b + l * Dc,
                                       lnm_g + l * Dc, lnm_b + l * Dc, h2_, BS);
        run_hgemm(h2_, w12_ + (long long)l * Mc * Dc, b1 + l * Mc, nullptr, nullptr,
                  nullptr, mb2_, BS, Mc, Dc, Mc, 1);
        run_hgemm(mb2_, w22_ + (long long)l * Dc * Mc, b2 + l * Dc, t_, nullptr,
                  t_, nullptr, BS, Dc, Mc, Dc, 0);
    }

    // --- head ---
    layernorm_cls_kernel<<<Bc, 256>>>(t_, lnf_g, lnf_b, cls2_, Bc);
    run_hgemm(cls2_, wh2_, bhead, nullptr, nullptr, out, nullptr, Bc, NCc, Dc, NCc, 0);
    softmax_kernel<<<Bc, 256>>>(out, Bc, NCc);
}